// round 2
// baseline (speedup 1.0000x reference)
#include <cuda_runtime.h>
#include <math.h>

#define B     8
#define CIN   256
#define HID   256
#define HEADS 8
#define HD    32
#define KW    31
#define PAD   15
#define W     16384

// ---------------- scratch (device globals; no allocation allowed) ----------------
__device__ __align__(16) float g_qWk[CIN * HEADS];        // [D][h]
__device__ __align__(16) float g_qWkb[HEADS];
__device__ __align__(16) float g_rpe_exp[HEADS * KW];
__device__ __align__(16) float g_cexp[B * HEADS * W];     // exp(cost)
__device__ __align__(16) float g_invden[B * HEADS * W];   // 1 / conv(cost_exp)
__device__ __align__(16) float g_vc[B * HID * W];         // cost_exp * v
__device__ __align__(16) float g_r[B * HID * W];          // conv(vc) * invden

// ---------------- prep: q normalize, qWk, qWk_b, exp(rpe) ----------------
__global__ void prep_kernel(const float* __restrict__ query,
                            const float* __restrict__ Wk,
                            const float* __restrict__ Wkb,
                            const float* __restrict__ rpe)
{
    __shared__ float qs[HID];
    const int tid = threadIdx.x;      // 256 threads, warp == head
    const int h   = tid >> 5;
    const int d   = tid & 31;

    float qv = query[tid];
    float s  = qv * qv;
    #pragma unroll
    for (int o = 16; o; o >>= 1) s += __shfl_xor_sync(0xffffffffu, s, o);
    float q = qv / (sqrtf(s) + 1e-6f) * 0.17677669529663687f;  // /(norm+1e-6)/sqrt(32)
    qs[tid] = q;

    float bt = Wkb[tid] * q;
    #pragma unroll
    for (int o = 16; o; o >>= 1) bt += __shfl_xor_sync(0xffffffffu, bt, o);
    if (d == 0) g_qWkb[h] = bt;

    if (tid < HEADS * KW) g_rpe_exp[tid] = expf(rpe[tid]);
    __syncthreads();

    // qWk[D][h2] = sum_d q[h2,d] * Wk[D, h2*32+d]   (thread = D)
    const int D = tid;
    #pragma unroll
    for (int h2 = 0; h2 < HEADS; h2++) {
        float a = 0.f;
        #pragma unroll
        for (int d2 = 0; d2 < HD; d2++)
            a = fmaf(qs[h2 * HD + d2], Wk[(size_t)D * HID + h2 * HD + d2], a);
        g_qWk[D * HEADS + h2] = a;
    }
}

// ---------------- cost_exp[b,h,w] = exp(sum_D x[b,D,w] * qWk[D,h] + qWk_b[h]) ----------------
__global__ void cost_kernel(const float* __restrict__ x)
{
    const int b = blockIdx.z;
    const int w = blockIdx.x * 256 + threadIdx.x;
    __shared__ float qs[CIN][HEADS];   // 8 KB
    for (int i = threadIdx.x; i < CIN * HEADS; i += 256)
        ((float*)qs)[i] = g_qWk[i];
    __syncthreads();

    const float* xb = x + (size_t)b * CIN * W + w;
    float acc[HEADS];
    #pragma unroll
    for (int h = 0; h < HEADS; h++) acc[h] = g_qWkb[h];

    #pragma unroll 4
    for (int D = 0; D < CIN; D++) {
        float xv = xb[(size_t)D * W];
        #pragma unroll
        for (int h = 0; h < HEADS; h++)
            acc[h] = fmaf(xv, qs[D][h], acc[h]);
    }
    #pragma unroll
    for (int h = 0; h < HEADS; h++)
        g_cexp[((size_t)b * HEADS + h) * W + w] = expf(acc[h]);
}

// ---------------- invden[b,h,w] = 1 / sum_k rpe_exp[h,k] * cexp[b,h,w-15+k] ----------------
__global__ void denom_kernel()
{
    const int bh = blockIdx.y;         // b*HEADS + h
    const int h  = bh & 7;
    const int w0 = blockIdx.x * 1024;
    __shared__ float s[1024 + 2 * PAD];
    const float* src = g_cexp + (size_t)bh * W;
    for (int i = threadIdx.x; i < 1024 + 2 * PAD; i += 256) {
        int w = w0 + i - PAD;
        s[i] = (w >= 0 && w < W) ? src[w] : 0.f;
    }
    float rp[KW];
    #pragma unroll
    for (int k = 0; k < KW; k++) rp[k] = g_rpe_exp[h * KW + k];
    __syncthreads();
    #pragma unroll
    for (int j = 0; j < 4; j++) {
        int i = threadIdx.x + j * 256;
        float a = 0.f;
        #pragma unroll
        for (int k = 0; k < KW; k++) a = fmaf(rp[k], s[i + k], a);
        g_invden[(size_t)bh * W + w0 + i] = 1.f / a;
    }
}

// ---------------- r[b,c,w] = (sum_k rpe_exp[h,k]*vc[b,c,w-15+k]) * invden[b,h,w] ----------------
__global__ void conv_kernel()
{
    const int bc = blockIdx.y;         // b*HID + c
    const int b  = bc >> 8;
    const int c  = bc & 255;
    const int h  = c >> 5;
    const int w0 = blockIdx.x * 1024;
    __shared__ float s[1024 + 2 * PAD];
    const float* src = g_vc + (size_t)bc * W;
    for (int i = threadIdx.x; i < 1024 + 2 * PAD; i += 256) {
        int w = w0 + i - PAD;
        s[i] = (w >= 0 && w < W) ? src[w] : 0.f;
    }
    float rp[KW];
    #pragma unroll
    for (int k = 0; k < KW; k++) rp[k] = g_rpe_exp[h * KW + k];
    __syncthreads();
    const float* inv = g_invden + ((size_t)b * HEADS + h) * W + w0;
    float* dst = g_r + (size_t)bc * W + w0;
    #pragma unroll
    for (int j = 0; j < 4; j++) {
        int i = threadIdx.x + j * 256;
        float a = 0.f;
        #pragma unroll
        for (int k = 0; k < KW; k++) a = fmaf(rp[k], s[i + k], a);
        dst[i] = a * inv[i];
    }
}

// ---------------- 128x128 tile SGEMM (K=256), 8x8 micro-tile ----------------
// MODE 0: C = cexp .* (Wv @ x + bv)  -> g_vc       (Bsrc = x input)
// MODE 1: C = Wo @ g_r + bo          -> Cdst(d_out)
template <int MODE>
__global__ __launch_bounds__(256, 2)
void gemm128(const float* __restrict__ Bsrc, const float* __restrict__ Wmat,
             const float* __restrict__ bias, float* __restrict__ Cdst)
{
    const int b  = blockIdx.z;
    const int o0 = blockIdx.y * 128;
    const int w0 = blockIdx.x * 128;
    __shared__ float As[16][128];      // [k][o]
    __shared__ float Bs[16][128];      // [k][w]
    const int tid = threadIdx.x;
    const int tx  = tid & 15;
    const int ty  = tid >> 4;

    float acc[8][8];
    #pragma unroll
    for (int i = 0; i < 8; i++)
        #pragma unroll
        for (int j = 0; j < 8; j++) acc[i][j] = 0.f;

    const float* Bb = (MODE == 0) ? (Bsrc + (size_t)b * CIN * W)
                                  : (g_r + (size_t)b * HID * W);

    for (int k0 = 0; k0 < 256; k0 += 16) {
        #pragma unroll
        for (int r = 0; r < 2; r++) {
            int idx = tid + r * 256;
            int o   = idx >> 2;                 // 0..127
            int k4  = (idx & 3) * 4;
            float4 v = *(const float4*)&Wmat[(size_t)(o0 + o) * 256 + k0 + k4];
            As[k4 + 0][o] = v.x; As[k4 + 1][o] = v.y;
            As[k4 + 2][o] = v.z; As[k4 + 3][o] = v.w;
        }
        #pragma unroll
        for (int r = 0; r < 2; r++) {
            int idx = tid + r * 256;
            int row = idx >> 5;                 // 0..15
            int c4  = (idx & 31) * 4;
            *(float4*)&Bs[row][c4] =
                *(const float4*)&Bb[(size_t)(k0 + row) * W + w0 + c4];
        }
        __syncthreads();
        #pragma unroll
        for (int k = 0; k < 16; k++) {
            float a[8], bb[8];
            *(float4*)&a[0]  = *(const float4*)&As[k][ty * 8];
            *(float4*)&a[4]  = *(const float4*)&As[k][ty * 8 + 4];
            *(float4*)&bb[0] = *(const float4*)&Bs[k][tx * 8];
            *(float4*)&bb[4] = *(const float4*)&Bs[k][tx * 8 + 4];
            #pragma unroll
            for (int i = 0; i < 8; i++)
                #pragma unroll
                for (int j = 0; j < 8; j++)
                    acc[i][j] = fmaf(a[i], bb[j], acc[i][j]);
        }
        __syncthreads();
    }

    // epilogue: 8 rows per thread all share one head (ty*8 aligned within 32)
    float ce[8];
    if (MODE == 0) {
        const int h = (o0 + ty * 8) >> 5;
        const float* cp = g_cexp + ((size_t)b * HEADS + h) * W + w0 + tx * 8;
        #pragma unroll
        for (int j = 0; j < 8; j++) ce[j] = cp[j];
    }
    #pragma unroll
    for (int i = 0; i < 8; i++) {
        int o = o0 + ty * 8 + i;
        float bv = bias[o];
        float outv[8];
        #pragma unroll
        for (int j = 0; j < 8; j++) {
            float c = acc[i][j] + bv;
            outv[j] = (MODE == 0) ? c * ce[j] : c;
        }
        float* dst = ((MODE == 0) ? g_vc : Cdst) + ((size_t)b * HID + o) * W + w0 + tx * 8;
        *(float4*)&dst[0] = *(float4*)&outv[0];
        *(float4*)&dst[4] = *(float4*)&outv[4];
    }
}

// ---------------- launch ----------------
extern "C" void kernel_launch(void* const* d_in, const int* in_sizes, int n_in,
                              void* d_out, int out_size)
{
    const float* x     = (const float*)d_in[0];
    const float* query = (const float*)d_in[1];
    const float* Wk    = (const float*)d_in[2];
    const float* Wkb   = (const float*)d_in[3];
    const float* rpe   = (const float*)d_in[4];
    const float* Wv    = (const float*)d_in[5];
    const float* bv    = (const float*)d_in[6];
    const float* Wo    = (const float*)d_in[7];
    const float* bo    = (const float*)d_in[8];
    float* out = (float*)d_out;

    prep_kernel<<<1, 256>>>(query, Wk, Wkb, rpe);
    cost_kernel<<<dim3(W / 256, 1, B), 256>>>(x);
    denom_kernel<<<dim3(W / 1024, B * HEADS), 256>>>();
    gemm128<0><<<dim3(W / 128, HID / 128, B), 256>>>(x, Wv, bv, nullptr);
    conv_kernel<<<dim3(W / 1024, B * HID), 256>>>();
    gemm128<1><<<dim3(W / 128, HID / 128, B), 256>>>(nullptr, Wo, bo, out);
}

// round 9
// speedup vs baseline: 1.1243x; 1.1243x over previous
#include <cuda_runtime.h>
#include <math.h>

#define B     8
#define CIN   256
#define HID   256
#define HEADS 8
#define HD    32
#define KW    31
#define PAD   15
#define W     16384

// ---------------- scratch (device globals; no allocation allowed) ----------------
__device__ __align__(16) float g_qWk[CIN * HEADS];        // [D][h]
__device__ __align__(16) float g_qWkb[HEADS];
__device__ __align__(16) float g_rpe_exp[HEADS * KW];
__device__ __align__(16) float g_cexp[B * HEADS * W];     // exp(cost)
__device__ __align__(16) float g_invden[B * HEADS * W];   // 1 / conv(cost_exp)
__device__ __align__(16) float g_vc[B * HID * W];         // cost_exp * v
__device__ __align__(16) float g_r[B * HID * W];          // conv(vc) * invden

// ---------------- prep: q normalize, qWk, qWk_b, exp(rpe) ----------------
__global__ void prep_kernel(const float* __restrict__ query,
                            const float* __restrict__ Wk,
                            const float* __restrict__ Wkb,
                            const float* __restrict__ rpe)
{
    __shared__ float qs[HID];
    const int tid = threadIdx.x;      // 256 threads, warp == head
    const int h   = tid >> 5;
    const int d   = tid & 31;

    float qv = query[tid];
    float s  = qv * qv;
    #pragma unroll
    for (int o = 16; o; o >>= 1) s += __shfl_xor_sync(0xffffffffu, s, o);
    float q = qv / (sqrtf(s) + 1e-6f) * 0.17677669529663687f;  // /(norm+1e-6)/sqrt(32)
    qs[tid] = q;

    float bt = Wkb[tid] * q;
    #pragma unroll
    for (int o = 16; o; o >>= 1) bt += __shfl_xor_sync(0xffffffffu, bt, o);
    if (d == 0) g_qWkb[h] = bt;

    if (tid < HEADS * KW) g_rpe_exp[tid] = expf(rpe[tid]);
    __syncthreads();

    // qWk[D][h2] = sum_d q[h2,d] * Wk[D, h2*32+d]   (thread = D)
    const int D = tid;
    #pragma unroll
    for (int h2 = 0; h2 < HEADS; h2++) {
        float a = 0.f;
        #pragma unroll
        for (int d2 = 0; d2 < HD; d2++)
            a = fmaf(qs[h2 * HD + d2], Wk[(size_t)D * HID + h2 * HD + d2], a);
        g_qWk[D * HEADS + h2] = a;
    }
}

// ---------------- cost_exp[b,h,w] = exp(sum_D x[b,D,w] * qWk[D,h] + qWk_b[h]) ----------------
__global__ void cost_kernel(const float* __restrict__ x)
{
    const int b = blockIdx.z;
    const int w = blockIdx.x * 256 + threadIdx.x;
    __shared__ float qs[CIN][HEADS];   // 8 KB
    for (int i = threadIdx.x; i < CIN * HEADS; i += 256)
        ((float*)qs)[i] = g_qWk[i];
    __syncthreads();

    const float* xb = x + (size_t)b * CIN * W + w;
    float acc[HEADS];
    #pragma unroll
    for (int h = 0; h < HEADS; h++) acc[h] = g_qWkb[h];

    #pragma unroll 4
    for (int D = 0; D < CIN; D++) {
        float xv = xb[(size_t)D * W];
        #pragma unroll
        for (int h = 0; h < HEADS; h++)
            acc[h] = fmaf(xv, qs[D][h], acc[h]);
    }
    #pragma unroll
    for (int h = 0; h < HEADS; h++)
        g_cexp[((size_t)b * HEADS + h) * W + w] = expf(acc[h]);
}

// ---------------- invden[b,h,w] = 1 / sum_k rpe_exp[h,k] * cexp[b,h,w-15+k] ----------------
__global__ void denom_kernel()
{
    const int bh = blockIdx.y;         // b*HEADS + h
    const int h  = bh & 7;
    const int w0 = blockIdx.x * 1024;
    __shared__ float s[1024 + 2 * PAD];
    const float* src = g_cexp + (size_t)bh * W;
    for (int i = threadIdx.x; i < 1024 + 2 * PAD; i += 256) {
        int w = w0 + i - PAD;
        s[i] = (w >= 0 && w < W) ? src[w] : 0.f;
    }
    float rp[KW];
    #pragma unroll
    for (int k = 0; k < KW; k++) rp[k] = g_rpe_exp[h * KW + k];
    __syncthreads();
    #pragma unroll
    for (int j = 0; j < 4; j++) {
        int i = threadIdx.x + j * 256;
        float a = 0.f;
        #pragma unroll
        for (int k = 0; k < KW; k++) a = fmaf(rp[k], s[i + k], a);
        g_invden[(size_t)bh * W + w0 + i] = 1.f / a;
    }
}

// ---------------- r[b,c,w] = (sum_k rpe_exp[h,k]*vc[b,c,w-15+k]) * invden[b,h,w] ----------------
__global__ void conv_kernel()
{
    const int bc = blockIdx.y;         // b*HID + c
    const int b  = bc >> 8;
    const int c  = bc & 255;
    const int h  = c >> 5;
    const int w0 = blockIdx.x * 1024;
    __shared__ float s[1024 + 2 * PAD];
    const float* src = g_vc + (size_t)bc * W;
    for (int i = threadIdx.x; i < 1024 + 2 * PAD; i += 256) {
        int w = w0 + i - PAD;
        s[i] = (w >= 0 && w < W) ? src[w] : 0.f;
    }
    float rp[KW];
    #pragma unroll
    for (int k = 0; k < KW; k++) rp[k] = g_rpe_exp[h * KW + k];
    __syncthreads();
    const float* inv = g_invden + ((size_t)b * HEADS + h) * W + w0;
    float* dst = g_r + (size_t)bc * W + w0;
    #pragma unroll
    for (int j = 0; j < 4; j++) {
        int i = threadIdx.x + j * 256;
        float a = 0.f;
        #pragma unroll
        for (int k = 0; k < KW; k++) a = fmaf(rp[k], s[i + k], a);
        dst[i] = a * inv[i];
    }
}

// ---------------- 128x128 tile SGEMM (K=256), 8x8 micro-tile ----------------
// Conflict-free B mapping: thread columns {tx*4..+3} and {64+tx*4..+3}
// Double-buffered smem, one __syncthreads per k-tile.
// MODE 0: C = cexp .* (Wv @ x + bv)  -> g_vc       (Bsrc = x input)
// MODE 1: C = Wo @ g_r + bo          -> Cdst(d_out)
template <int MODE>
__global__ __launch_bounds__(256, 2)
void gemm128(const float* __restrict__ Bsrc, const float* __restrict__ Wmat,
             const float* __restrict__ bias, float* __restrict__ Cdst)
{
    const int b  = blockIdx.z;
    const int o0 = blockIdx.y * 128;
    const int w0 = blockIdx.x * 128;
    __shared__ float As[2][16][128];      // [buf][k][o]
    __shared__ float Bs[2][16][128];      // [buf][k][w]
    const int tid = threadIdx.x;
    const int tx  = tid & 15;
    const int ty  = tid >> 4;

    // load indices (tile load, 2 rounds of 256 threads)
    const int aO  = tid >> 2;             // 0..63 (round adds 64)
    const int aK4 = (tid & 3) * 4;
    const int bRow = tid >> 5;            // 0..7 (round adds 8)
    const int bC4  = (tid & 31) * 4;

    float acc[8][8];
    #pragma unroll
    for (int i = 0; i < 8; i++)
        #pragma unroll
        for (int j = 0; j < 8; j++) acc[i][j] = 0.f;

    const float* Bb = (MODE == 0) ? (Bsrc + (size_t)b * CIN * W)
                                  : (g_r + (size_t)b * HID * W);

    // ---- load tile 0 directly into buffer 0 ----
    {
        #pragma unroll
        for (int r = 0; r < 2; r++) {
            int o = aO + r * 64;
            float4 v = *(const float4*)&Wmat[(size_t)(o0 + o) * 256 + aK4];
            As[0][aK4 + 0][o] = v.x; As[0][aK4 + 1][o] = v.y;
            As[0][aK4 + 2][o] = v.z; As[0][aK4 + 3][o] = v.w;
        }
        #pragma unroll
        for (int r = 0; r < 2; r++) {
            int row = bRow + r * 8;
            *(float4*)&Bs[0][row][bC4] =
                *(const float4*)&Bb[(size_t)row * W + w0 + bC4];
        }
    }
    __syncthreads();

    for (int kt = 0; kt < 16; kt++) {
        const int cur = kt & 1;
        float4 pa0, pa1, pb0, pb1;
        if (kt < 15) {
            const int k0 = (kt + 1) * 16;
            pa0 = *(const float4*)&Wmat[(size_t)(o0 + aO) * 256 + k0 + aK4];
            pa1 = *(const float4*)&Wmat[(size_t)(o0 + aO + 64) * 256 + k0 + aK4];
            pb0 = *(const float4*)&Bb[(size_t)(k0 + bRow) * W + w0 + bC4];
            pb1 = *(const float4*)&Bb[(size_t)(k0 + bRow + 8) * W + w0 + bC4];
        }
        #pragma unroll
        for (int k = 0; k < 16; k++) {
            float a[8], bb[8];
            *(float4*)&a[0]  = *(const float4*)&As[cur][k][ty * 8];
            *(float4*)&a[4]  = *(const float4*)&As[cur][k][ty * 8 + 4];
            *(float4*)&bb[0] = *(const float4*)&Bs[cur][k][tx * 4];
            *(float4*)&bb[4] = *(const float4*)&Bs[cur][k][64 + tx * 4];
            #pragma unroll
            for (int i = 0; i < 8; i++)
                #pragma unroll
                for (int j = 0; j < 8; j++)
                    acc[i][j] = fmaf(a[i], bb[j], acc[i][j]);
        }
        if (kt < 15) {
            const int nxt = cur ^ 1;
            As[nxt][aK4 + 0][aO] = pa0.x; As[nxt][aK4 + 1][aO] = pa0.y;
            As[nxt][aK4 + 2][aO] = pa0.z; As[nxt][aK4 + 3][aO] = pa0.w;
            As[nxt][aK4 + 0][aO + 64] = pa1.x; As[nxt][aK4 + 1][aO + 64] = pa1.y;
            As[nxt][aK4 + 2][aO + 64] = pa1.z; As[nxt][aK4 + 3][aO + 64] = pa1.w;
            *(float4*)&Bs[nxt][bRow][bC4]     = pb0;
            *(float4*)&Bs[nxt][bRow + 8][bC4] = pb1;
            __syncthreads();
        }
    }

    // epilogue: rows ty*8..ty*8+7 (one head), cols {w0+tx*4..} and {w0+64+tx*4..}
    float ce[8];
    if (MODE == 0) {
        const int h = (o0 + ty * 8) >> 5;
        const float* cp = g_cexp + ((size_t)b * HEADS + h) * W + w0;
        #pragma unroll
        for (int j = 0; j < 4; j++) ce[j]     = cp[tx * 4 + j];
        #pragma unroll
        for (int j = 0; j < 4; j++) ce[4 + j] = cp[64 + tx * 4 + j];
    }
    #pragma unroll
    for (int i = 0; i < 8; i++) {
        int o = o0 + ty * 8 + i;
        float bv = bias[o];
        float outv[8];
        #pragma unroll
        for (int j = 0; j < 8; j++) {
            float c = acc[i][j] + bv;
            outv[j] = (MODE == 0) ? c * ce[j] : c;
        }
        float* dst = ((MODE == 0) ? g_vc : Cdst) + ((size_t)b * HID + o) * W + w0;
        *(float4*)&dst[tx * 4]      = *(float4*)&outv[0];
        *(float4*)&dst[64 + tx * 4] = *(float4*)&outv[4];
    }
}

// ---------------- launch ----------------
extern "C" void kernel_launch(void* const* d_in, const int* in_sizes, int n_in,
                              void* d_out, int out_size)
{
    const float* x     = (const float*)d_in[0];
    const float* query = (const float*)d_in[1];
    const float* Wk    = (const float*)d_in[2];
    const float* Wkb   = (const float*)d_in[3];
    const float* rpe   = (const float*)d_in[4];
    const float* Wv    = (const float*)d_in[5];
    const float* bv    = (const float*)d_in[6];
    const float* Wo    = (const float*)d_in[7];
    const float* bo    = (const float*)d_in[8];
    float* out = (float*)d_out;

    prep_kernel<<<1, 256>>>(query, Wk, Wkb, rpe);
    cost_kernel<<<dim3(W / 256, 1, B), 256>>>(x);
    denom_kernel<<<dim3(W / 1024, B * HEADS), 256>>>();
    gemm128<0><<<dim3(W / 128, HID / 128, B), 256>>>(x, Wv, bv, nullptr);
    conv_kernel<<<dim3(W / 1024, B * HID), 256>>>();
    gemm128<1><<<dim3(W / 128, HID / 128, B), 256>>>(nullptr, Wo, bo, out);
}

// round 15
// speedup vs baseline: 1.6139x; 1.4355x over previous
#include <cuda_runtime.h>
#include <cuda_bf16.h>
#include <math.h>
#include <stdint.h>
#include <string.h>

#define B     8
#define CIN   256
#define HID   256
#define HEADS 8
#define HD    32
#define KW    31
#define PAD   15
#define W     16384

// ---------------- scratch ----------------
__device__ __align__(16) float g_qWk[CIN * HEADS];
__device__ __align__(16) float g_qWkb[HEADS];
__device__ __align__(16) float g_rpe_exp[HEADS * KW];
__device__ __align__(16) float g_cexp[B * HEADS * W];
__device__ __align__(16) float g_invden[B * HEADS * W];
__device__ __align__(16) float g_vc[B * HID * W];
__device__ __align__(16) float g_r[B * HID * W];

// ---------------- helpers ----------------
__device__ __forceinline__ uint32_t smem_u32(const void* p) {
    uint32_t a;
    asm("{ .reg .u64 t; cvta.to.shared.u64 t, %1; cvt.u32.u64 %0, t; }"
        : "=r"(a) : "l"(p));
    return a;
}
__device__ __forceinline__ uint32_t bpack(__nv_bfloat16 a, __nv_bfloat16 b) {
    __nv_bfloat162 t = __halves2bfloat162(a, b);
    uint32_t u;
    memcpy(&u, &t, 4);
    return u;
}
__device__ __forceinline__ void ldsm4(uint32_t& r0, uint32_t& r1, uint32_t& r2,
                                      uint32_t& r3, uint32_t addr) {
    asm volatile("ldmatrix.sync.aligned.m8n8.x4.shared.b16 {%0,%1,%2,%3}, [%4];"
                 : "=r"(r0), "=r"(r1), "=r"(r2), "=r"(r3) : "r"(addr));
}
__device__ __forceinline__ void ldsm4t(uint32_t& r0, uint32_t& r1, uint32_t& r2,
                                       uint32_t& r3, uint32_t addr) {
    asm volatile("ldmatrix.sync.aligned.m8n8.x4.trans.shared.b16 {%0,%1,%2,%3}, [%4];"
                 : "=r"(r0), "=r"(r1), "=r"(r2), "=r"(r3) : "r"(addr));
}
__device__ __forceinline__ void mma16816(float* c, const uint32_t* a,
                                         const uint32_t* b) {
    asm volatile(
        "mma.sync.aligned.m16n8k16.row.col.f32.bf16.bf16.f32 "
        "{%0,%1,%2,%3}, {%4,%5,%6,%7}, {%8,%9}, {%0,%1,%2,%3};"
        : "+f"(c[0]), "+f"(c[1]), "+f"(c[2]), "+f"(c[3])
        : "r"(a[0]), "r"(a[1]), "r"(a[2]), "r"(a[3]), "r"(b[0]), "r"(b[1]));
}

// SMEM (bytes): padded rows of 72 bf16 = 144 B (conflict-free LDSM: 4-bank shift/row)
#define AROW     144
#define SM_A_HI  0
#define SM_A_LO  18432              // 128*144
#define SM_B_HI  36864
#define SM_B_LO  46080              // + 64*144
#define SM_TOTAL 55296

// ---------------- prep ----------------
__global__ void prep_kernel(const float* __restrict__ query,
                            const float* __restrict__ Wk,
                            const float* __restrict__ Wkb,
                            const float* __restrict__ rpe)
{
    __shared__ float qs[HID];
    const int tid = threadIdx.x;
    const int h   = tid >> 5;
    const int d   = tid & 31;

    float qv = query[tid];
    float s  = qv * qv;
    #pragma unroll
    for (int o = 16; o; o >>= 1) s += __shfl_xor_sync(0xffffffffu, s, o);
    float q = qv / (sqrtf(s) + 1e-6f) * 0.17677669529663687f;
    qs[tid] = q;

    float bt = Wkb[tid] * q;
    #pragma unroll
    for (int o = 16; o; o >>= 1) bt += __shfl_xor_sync(0xffffffffu, bt, o);
    if (d == 0) g_qWkb[h] = bt;

    if (tid < HEADS * KW) g_rpe_exp[tid] = expf(rpe[tid]);
    __syncthreads();

    const int D = tid;
    #pragma unroll
    for (int h2 = 0; h2 < HEADS; h2++) {
        float a = 0.f;
        #pragma unroll
        for (int d2 = 0; d2 < HD; d2++)
            a = fmaf(qs[h2 * HD + d2], Wk[(size_t)D * HID + h2 * HD + d2], a);
        g_qWk[D * HEADS + h2] = a;
    }
}

// ---------------- cost_exp ----------------
__global__ void cost_kernel(const float* __restrict__ x)
{
    const int b = blockIdx.z;
    const int w = blockIdx.x * 256 + threadIdx.x;
    __shared__ float qs[CIN][HEADS];
    for (int i = threadIdx.x; i < CIN * HEADS; i += 256)
        ((float*)qs)[i] = g_qWk[i];
    __syncthreads();

    const float* xb = x + (size_t)b * CIN * W + w;
    float acc[HEADS];
    #pragma unroll
    for (int h = 0; h < HEADS; h++) acc[h] = g_qWkb[h];

    #pragma unroll 4
    for (int D = 0; D < CIN; D++) {
        float xv = xb[(size_t)D * W];
        #pragma unroll
        for (int h = 0; h < HEADS; h++)
            acc[h] = fmaf(xv, qs[D][h], acc[h]);
    }
    #pragma unroll
    for (int h = 0; h < HEADS; h++)
        g_cexp[((size_t)b * HEADS + h) * W + w] = expf(acc[h]);
}

// ---------------- denom ----------------
__global__ void denom_kernel()
{
    const int bh = blockIdx.y;
    const int h  = bh & 7;
    const int w0 = blockIdx.x * 1024;
    __shared__ float s[1024 + 2 * PAD];
    const float* src = g_cexp + (size_t)bh * W;
    for (int i = threadIdx.x; i < 1024 + 2 * PAD; i += 256) {
        int w = w0 + i - PAD;
        s[i] = (w >= 0 && w < W) ? src[w] : 0.f;
    }
    float rp[KW];
    #pragma unroll
    for (int k = 0; k < KW; k++) rp[k] = g_rpe_exp[h * KW + k];
    __syncthreads();
    #pragma unroll
    for (int j = 0; j < 4; j++) {
        int i = threadIdx.x + j * 256;
        float a = 0.f;
        #pragma unroll
        for (int k = 0; k < KW; k++) a = fmaf(rp[k], s[i + k], a);
        g_invden[(size_t)bh * W + w0 + i] = 1.f / a;
    }
}

// ---------------- conv ----------------
__global__ void conv_kernel()
{
    const int bc = blockIdx.y;
    const int b  = bc >> 8;
    const int c  = bc & 255;
    const int h  = c >> 5;
    const int w0 = blockIdx.x * 1024;
    __shared__ float s[1024 + 2 * PAD];
    const float* src = g_vc + (size_t)bc * W;
    for (int i = threadIdx.x; i < 1024 + 2 * PAD; i += 256) {
        int w = w0 + i - PAD;
        s[i] = (w >= 0 && w < W) ? src[w] : 0.f;
    }
    float rp[KW];
    #pragma unroll
    for (int k = 0; k < KW; k++) rp[k] = g_rpe_exp[h * KW + k];
    __syncthreads();
    const float* inv = g_invden + ((size_t)b * HEADS + h) * W + w0;
    float* dst = g_r + (size_t)bc * W + w0;
    #pragma unroll
    for (int j = 0; j < 4; j++) {
        int i = threadIdx.x + j * 256;
        float a = 0.f;
        #pragma unroll
        for (int k = 0; k < KW; k++) a = fmaf(rp[k], s[i + k], a);
        dst[i] = a * inv[i];
    }
}

// ---------------- tensor-core GEMM via mma.sync (bf16 split-3) ----------------
// CTA tile: 128 o x 64 w, K = 256 in 4 chunks of 64.
// 8 warps as 4(o) x 2(w); warp tile 32 o x 32 w; m16n8k16 fragments.
// MODE 0: C = cexp .* (Wv@x + bv) -> g_vc ;  MODE 1: C = Wo@g_r + bo -> Cdst
template <int MODE>
__global__ __launch_bounds__(256, 2)
void gemm_tc(const float* __restrict__ Bsrc, const float* __restrict__ Wmat,
             const float* __restrict__ bias, float* __restrict__ Cdst)
{
    extern __shared__ char smem[];
    const int b   = blockIdx.z;
    const int o0  = blockIdx.y * 128;
    const int w0  = blockIdx.x * 64;
    const int tid = threadIdx.x;
    const int wid = tid >> 5;
    const int l   = tid & 31;
    const int wr  = wid >> 1;          // 0..3  o-quadrant
    const int wc  = wid & 1;           // 0..1  w-half
    const uint32_t sb = smem_u32(smem);

    // ldmatrix lane address components
    const int a_row  = ((l >> 3) & 1) * 8 + (l & 7);   // row within 16
    const int a_koff = (l >> 4) * 8;                    // k offset 0/8
    const uint32_t aL_hi = sb + SM_A_HI + (uint32_t)(a_row * AROW + a_koff * 2);
    const uint32_t aL_lo = sb + SM_A_LO + (uint32_t)(a_row * AROW + a_koff * 2);
    const uint32_t bL_hi = sb + SM_B_HI + (uint32_t)(a_row * AROW + a_koff * 2); // k-row, n-off
    const uint32_t bL_lo = sb + SM_B_LO + (uint32_t)(a_row * AROW + a_koff * 2);

    const float* Bb = (MODE == 0) ? (Bsrc + (size_t)b * CIN * W)
                                  : (g_r + (size_t)b * HID * W);

    float acc[2][4][4];
    #pragma unroll
    for (int i = 0; i < 2; i++)
        #pragma unroll
        for (int j = 0; j < 4; j++)
            #pragma unroll
            for (int k = 0; k < 4; k++) acc[i][j][k] = 0.f;

    for (int c = 0; c < 4; c++) {
        const int k0 = c * 64;
        if (c > 0) __syncthreads();          // protect smem reuse

        // --- stage A (weights): 128 o x 64 k -> hi/lo bf16, row pad 144B ---
        #pragma unroll
        for (int it = 0; it < 8; it++) {
            int idx = tid + it * 256;
            int kq  = idx & 15;
            int o   = idx >> 4;
            float4 v = *(const float4*)&Wmat[(size_t)(o0 + o) * 256 + k0 + kq * 4];
            __nv_bfloat16 h0 = __float2bfloat16(v.x), h1 = __float2bfloat16(v.y);
            __nv_bfloat16 h2 = __float2bfloat16(v.z), h3 = __float2bfloat16(v.w);
            __nv_bfloat16 e0 = __float2bfloat16(v.x - __bfloat162float(h0));
            __nv_bfloat16 e1 = __float2bfloat16(v.y - __bfloat162float(h1));
            __nv_bfloat16 e2 = __float2bfloat16(v.z - __bfloat162float(h2));
            __nv_bfloat16 e3 = __float2bfloat16(v.w - __bfloat162float(h3));
            uint32_t off = (uint32_t)(o * AROW + kq * 8);
            *(uint2*)(smem + SM_A_HI + off) = make_uint2(bpack(h0, h1), bpack(h2, h3));
            *(uint2*)(smem + SM_A_LO + off) = make_uint2(bpack(e0, e1), bpack(e2, e3));
        }
        // --- stage B: 64 k x 64 w ([k][n] row-major, natural from x layout) ---
        #pragma unroll
        for (int it = 0; it < 4; it++) {
            int idx = tid + it * 256;
            int wq  = idx & 15;
            int k   = idx >> 4;
            float4 v = *(const float4*)&Bb[(size_t)(k0 + k) * W + w0 + wq * 4];
            __nv_bfloat16 h0 = __float2bfloat16(v.x), h1 = __float2bfloat16(v.y);
            __nv_bfloat16 h2 = __float2bfloat16(v.z), h3 = __float2bfloat16(v.w);
            __nv_bfloat16 e0 = __float2bfloat16(v.x - __bfloat162float(h0));
            __nv_bfloat16 e1 = __float2bfloat16(v.y - __bfloat162float(h1));
            __nv_bfloat16 e2 = __float2bfloat16(v.z - __bfloat162float(h2));
            __nv_bfloat16 e3 = __float2bfloat16(v.w - __bfloat162float(h3));
            uint32_t off = (uint32_t)(k * AROW + wq * 8);
            *(uint2*)(smem + SM_B_HI + off) = make_uint2(bpack(h0, h1), bpack(h2, h3));
            *(uint2*)(smem + SM_B_LO + off) = make_uint2(bpack(e0, e1), bpack(e2, e3));
        }
        __syncthreads();

        #pragma unroll
        for (int ks = 0; ks < 4; ks++) {
            const uint32_t kc2 = (uint32_t)(ks * 16 * 2);   // byte offset of k16 step
            // A fragments: 2 m-tiles (hi + lo)
            uint32_t ah[2][4], al[2][4];
            #pragma unroll
            for (int mt = 0; mt < 2; mt++) {
                uint32_t roff = (uint32_t)((wr * 32 + mt * 16) * AROW) + kc2;
                ldsm4(ah[mt][0], ah[mt][1], ah[mt][2], ah[mt][3], aL_hi + roff);
                ldsm4(al[mt][0], al[mt][1], al[mt][2], al[mt][3], aL_lo + roff);
            }
            // B fragments: 2 groups of 16 n (hi + lo); reg pairs {0,1}=n0-7, {2,3}=n8-15
            uint32_t bh[2][4], bl[2][4];
            #pragma unroll
            for (int ng = 0; ng < 2; ng++) {
                uint32_t noff = (uint32_t)(ks * 16 * AROW + (wc * 32 + ng * 16) * 2);
                ldsm4t(bh[ng][0], bh[ng][1], bh[ng][2], bh[ng][3], bL_hi + noff);
                ldsm4t(bl[ng][0], bl[ng][1], bl[ng][2], bl[ng][3], bL_lo + noff);
            }
            // 3-pass split accumulate: hi*hi + hi*lo + lo*hi
            #pragma unroll
            for (int mt = 0; mt < 2; mt++)
                #pragma unroll
                for (int nt = 0; nt < 4; nt++) {
                    uint32_t* bphi = &bh[nt >> 1][(nt & 1) * 2];
                    uint32_t* bplo = &bl[nt >> 1][(nt & 1) * 2];
                    mma16816(acc[mt][nt], ah[mt], bphi);
                    mma16816(acc[mt][nt], ah[mt], bplo);
                    mma16816(acc[mt][nt], al[mt], bphi);
                }
        }
    }

    // ---- epilogue ----
    const int g = l >> 2;               // 0..7
    const int t = l & 3;                // 0..3
    #pragma unroll
    for (int mt = 0; mt < 2; mt++) {
        #pragma unroll
        for (int half = 0; half < 2; half++) {       // c0,c1 (row g) / c2,c3 (row g+8)
            int o = o0 + wr * 32 + mt * 16 + g + half * 8;
            float bv = bias[o];
            float* dst = ((MODE == 0) ? g_vc : Cdst) + ((size_t)b * HID + o) * W;
            const float* cp = g_cexp + ((size_t)b * HEADS + (o >> 5)) * W;
            #pragma unroll
            for (int nt = 0; nt < 4; nt++) {
                int w = w0 + wc * 32 + nt * 8 + t * 2;
                float c0 = acc[mt][nt][half * 2 + 0] + bv;
                float c1 = acc[mt][nt][half * 2 + 1] + bv;
                float2 f;
                if (MODE == 0) { f.x = c0 * cp[w]; f.y = c1 * cp[w + 1]; }
                else           { f.x = c0;         f.y = c1; }
                *(float2*)&dst[w] = f;
            }
        }
    }
}

// ---------------- launch ----------------
extern "C" void kernel_launch(void* const* d_in, const int* in_sizes, int n_in,
                              void* d_out, int out_size)
{
    const float* x     = (const float*)d_in[0];
    const float* query = (const float*)d_in[1];
    const float* Wk    = (const float*)d_in[2];
    const float* Wkb   = (const float*)d_in[3];
    const float* rpe   = (const float*)d_in[4];
    const float* Wv    = (const float*)d_in[5];
    const float* bv    = (const float*)d_in[6];
    const float* Wo    = (const float*)d_in[7];
    const float* bo    = (const float*)d_in[8];
    float* out = (float*)d_out;

    cudaFuncSetAttribute(gemm_tc<0>, cudaFuncAttributeMaxDynamicSharedMemorySize, SM_TOTAL);
    cudaFuncSetAttribute(gemm_tc<1>, cudaFuncAttributeMaxDynamicSharedMemorySize, SM_TOTAL);

    prep_kernel<<<1, 256>>>(query, Wk, Wkb, rpe);
    cost_kernel<<<dim3(W / 256, 1, B), 256>>>(x);
    denom_kernel<<<dim3(W / 1024, B * HEADS), 256>>>();
    gemm_tc<0><<<dim3(W / 64, HID / 128, B), 256, SM_TOTAL>>>(x, Wv, bv, nullptr);
    conv_kernel<<<dim3(W / 1024, B * HID), 256>>>();
    gemm_tc<1><<<dim3(W / 64, HID / 128, B), 256, SM_TOTAL>>>(nullptr, Wo, bo, out);
}